// round 1
// baseline (speedup 1.0000x reference)
#include <cuda_runtime.h>
#include <math.h>

#define BATCH   32768
#define KDIM    1280
#define HDIM    64
#define NQ      4
#define NLAYERS 2
#define NCLS    10

#define BM 128
#define BK 32
#define NTHREADS 256

#define AS_PITCH (BM + 1)   // 129, conflict-free transposed stores
#define BS_PITCH (HDIM + 1) // 65
#define HS_PITCH (HDIM + 1) // 65

#define PI_HALF 1.57079632679489662f

// shared main buffer: max(GEMM tiles, epilogue H tile)
// GEMM: 32*129 + 32*65 = 6208 floats ; epilogue: 128*65 = 8320 floats
#define SMEM_MAIN_FLOATS 8320

__global__ __launch_bounds__(NTHREADS, 2)
void qh_fused_kernel(const float* __restrict__ x,
                     const float* __restrict__ W1,
                     const float* __restrict__ b1,
                     const float* __restrict__ bn_g,
                     const float* __restrict__ bn_b,
                     const float* __restrict__ bn_m,
                     const float* __restrict__ bn_v,
                     const float* __restrict__ W2,
                     const float* __restrict__ b2,
                     const float* __restrict__ qw,
                     const float* __restrict__ W3,
                     const float* __restrict__ b3,
                     float* __restrict__ out)
{
    __shared__ float smem_main[SMEM_MAIN_FLOATS];
    __shared__ float W2s[NQ * HDIM];     // 256
    __shared__ float scale_s[HDIM];
    __shared__ float shift_s[HDIM];
    __shared__ float b1s[HDIM];
    __shared__ float qtrig[NLAYERS * NQ * 4]; // cry,sry,crz,srz per (l,i)
    __shared__ float W3s[NCLS * NQ];
    __shared__ float b3s[NCLS];
    __shared__ float b2s[NQ];

    const int tid = threadIdx.x;

    // ---- per-block constant prep ----
    if (tid < HDIM) {
        b1s[tid] = b1[tid];
        float sc = bn_g[tid] * rsqrtf(bn_v[tid] + 1e-5f);
        scale_s[tid] = sc;
        shift_s[tid] = bn_b[tid] - bn_m[tid] * sc;
    }
    if (tid < NQ * HDIM) W2s[tid] = W2[tid];
    if (tid < NLAYERS * NQ) {
        float a0 = qw[tid * 2 + 0] * 0.5f;
        float a1 = qw[tid * 2 + 1] * 0.5f;
        qtrig[tid * 4 + 0] = cosf(a0);
        qtrig[tid * 4 + 1] = sinf(a0);
        qtrig[tid * 4 + 2] = cosf(a1);
        qtrig[tid * 4 + 3] = sinf(a1);
    }
    if (tid < NCLS * NQ) W3s[tid] = W3[tid];
    if (tid < NCLS)      b3s[tid] = b3[tid];
    if (tid < NQ)        b2s[tid] = b2[tid];
    __syncthreads();

    // ---- GEMM1: h[BM][64] = x[rowBase:rowBase+BM, :] @ W1^T ----
    float* As = smem_main;                 // [BK][AS_PITCH] transposed x tile
    float* Bs = smem_main + BK * AS_PITCH; // [BK][BS_PITCH] transposed W1 tile

    const int rowBase = blockIdx.x * BM;
    const int ty = tid >> 4;   // 0..15 -> rows ty*8 .. ty*8+7
    const int tx = tid & 15;   // 0..15 -> cols tx*4 .. tx*4+3

    float acc[8][4];
    #pragma unroll
    for (int i = 0; i < 8; ++i)
        #pragma unroll
        for (int j = 0; j < 4; ++j) acc[i][j] = 0.f;

    const int lrow = tid >> 3;  // 0..31
    const int lc4  = tid & 7;   // 0..7  (float4 index within 32-wide K slab)

    for (int kt = 0; kt < KDIM / BK; ++kt) {
        const int k0 = kt * BK;

        // load x tile: 128 rows x 32 cols, transposed into As[k][row]
        #pragma unroll
        for (int p = 0; p < 4; ++p) {
            const int row = p * 32 + lrow;
            float4 v = *(const float4*)&x[(rowBase + row) * KDIM + k0 + lc4 * 4];
            As[(lc4 * 4 + 0) * AS_PITCH + row] = v.x;
            As[(lc4 * 4 + 1) * AS_PITCH + row] = v.y;
            As[(lc4 * 4 + 2) * AS_PITCH + row] = v.z;
            As[(lc4 * 4 + 3) * AS_PITCH + row] = v.w;
        }
        // load W1 tile: 64 rows x 32 cols, transposed into Bs[k][h]
        #pragma unroll
        for (int p = 0; p < 2; ++p) {
            const int h = p * 32 + lrow;
            float4 v = *(const float4*)&W1[h * KDIM + k0 + lc4 * 4];
            Bs[(lc4 * 4 + 0) * BS_PITCH + h] = v.x;
            Bs[(lc4 * 4 + 1) * BS_PITCH + h] = v.y;
            Bs[(lc4 * 4 + 2) * BS_PITCH + h] = v.z;
            Bs[(lc4 * 4 + 3) * BS_PITCH + h] = v.w;
        }
        __syncthreads();

        #pragma unroll
        for (int k = 0; k < BK; ++k) {
            float a[8], b[4];
            #pragma unroll
            for (int i = 0; i < 8; ++i) a[i] = As[k * AS_PITCH + ty * 8 + i];
            #pragma unroll
            for (int j = 0; j < 4; ++j) b[j] = Bs[k * BS_PITCH + tx * 4 + j];
            #pragma unroll
            for (int i = 0; i < 8; ++i)
                #pragma unroll
                for (int j = 0; j < 4; ++j)
                    acc[i][j] = fmaf(a[i], b[j], acc[i][j]);
        }
        __syncthreads();
    }

    // ---- epilogue part 1: bias + relu + batchnorm -> Hs ----
    float* Hs = smem_main; // [BM][HS_PITCH]
    #pragma unroll
    for (int i = 0; i < 8; ++i) {
        const int r = ty * 8 + i;
        #pragma unroll
        for (int j = 0; j < 4; ++j) {
            const int h = tx * 4 + j;
            float v = acc[i][j] + b1s[h];
            v = fmaxf(v, 0.f);
            v = v * scale_s[h] + shift_s[h];
            Hs[r * HS_PITCH + h] = v;
        }
    }
    __syncthreads();

    // ---- epilogue part 2: one thread per row ----
    if (tid < BM) {
        const float* hr = &Hs[tid * HS_PITCH];

        // xq = tanh(h @ W2^T + b2)
        float xq[NQ];
        #pragma unroll
        for (int q = 0; q < NQ; ++q) {
            float s = b2s[q];
            const float* w2 = &W2s[q * HDIM];
            #pragma unroll
            for (int h = 0; h < HDIM; ++h) s = fmaf(hr[h], w2[h], s);
            xq[q] = tanhf(s);
        }

        // 4-qubit statevector in registers. index bit for wire w: (idx >> (3-w)) & 1
        float re[16], im[16];
        #pragma unroll
        for (int i = 0; i < 16; ++i) { re[i] = 0.f; im[i] = 0.f; }
        re[0] = 1.f;

        // initial RY(ang_w) encoders, ang = tanh(xq)*pi, half-angle = tanh(xq)*pi/2
        #pragma unroll
        for (int w = 0; w < NQ; ++w) {
            const float half = tanhf(xq[w]) * PI_HALF;
            const float c = cosf(half), s = sinf(half);
            const int st = 8 >> w;
            #pragma unroll
            for (int i = 0; i < 16; ++i) {
                if ((i & st) == 0) {
                    float r0 = re[i],      i0 = im[i];
                    float r1 = re[i + st], i1 = im[i + st];
                    re[i]      = c * r0 - s * r1;
                    im[i]      = c * i0 - s * i1;
                    re[i + st] = s * r0 + c * r1;
                    im[i + st] = s * i0 + c * i1;
                }
            }
        }

        // variational layers
        #pragma unroll
        for (int l = 0; l < NLAYERS; ++l) {
            #pragma unroll
            for (int w = 0; w < NQ; ++w) {
                const float cry = qtrig[(l * NQ + w) * 4 + 0];
                const float sry = qtrig[(l * NQ + w) * 4 + 1];
                const float crz = qtrig[(l * NQ + w) * 4 + 2];
                const float srz = qtrig[(l * NQ + w) * 4 + 3];
                const int st = 8 >> w;
                #pragma unroll
                for (int i = 0; i < 16; ++i) {
                    if ((i & st) == 0) {
                        // RY
                        float r0 = re[i],      i0 = im[i];
                        float r1 = re[i + st], i1 = im[i + st];
                        float nr0 = cry * r0 - sry * r1;
                        float ni0 = cry * i0 - sry * i1;
                        float nr1 = sry * r0 + cry * r1;
                        float ni1 = sry * i0 + cry * i1;
                        // RZ: amp0 *= e^{-i th/2}, amp1 *= e^{+i th/2}
                        re[i]      = nr0 * crz + ni0 * srz;
                        im[i]      = ni0 * crz - nr0 * srz;
                        re[i + st] = nr1 * crz - ni1 * srz;
                        im[i + st] = ni1 * crz + nr1 * srz;
                    }
                }
            }
            // CNOT ring: control w, target (w+1)%4
            #pragma unroll
            for (int w = 0; w < NQ; ++w) {
                const int cs = 8 >> w;
                const int ts = 8 >> ((w + 1) & 3);
                #pragma unroll
                for (int i = 0; i < 16; ++i) {
                    if ((i & cs) != 0 && (i & ts) == 0) {
                        float tr = re[i]; re[i] = re[i + ts]; re[i + ts] = tr;
                        float ti = im[i]; im[i] = im[i + ts]; im[i + ts] = ti;
                    }
                }
            }
        }

        // z expectations
        float z[NQ] = {0.f, 0.f, 0.f, 0.f};
        #pragma unroll
        for (int i = 0; i < 16; ++i) {
            const float p = re[i] * re[i] + im[i] * im[i];
            #pragma unroll
            for (int w = 0; w < NQ; ++w)
                z[w] += ((i >> (3 - w)) & 1) ? -p : p;
        }

        // final classifier
        const int r = rowBase + tid;
        #pragma unroll
        for (int c = 0; c < NCLS; ++c) {
            float s = b3s[c];
            #pragma unroll
            for (int q = 0; q < NQ; ++q) s = fmaf(z[q], W3s[c * NQ + q], s);
            out[r * NCLS + c] = s;
        }
    }
}

extern "C" void kernel_launch(void* const* d_in, const int* in_sizes, int n_in,
                              void* d_out, int out_size)
{
    const float* x    = (const float*)d_in[0];
    const float* W1   = (const float*)d_in[1];
    const float* b1   = (const float*)d_in[2];
    const float* bn_g = (const float*)d_in[3];
    const float* bn_b = (const float*)d_in[4];
    const float* bn_m = (const float*)d_in[5];
    const float* bn_v = (const float*)d_in[6];
    const float* W2   = (const float*)d_in[7];
    const float* b2   = (const float*)d_in[8];
    const float* qw   = (const float*)d_in[9];
    const float* W3   = (const float*)d_in[10];
    const float* b3   = (const float*)d_in[11];
    float* out = (float*)d_out;

    dim3 grid(BATCH / BM);
    dim3 block(NTHREADS);
    qh_fused_kernel<<<grid, block>>>(x, W1, b1, bn_g, bn_b, bn_m, bn_v,
                                     W2, b2, qw, W3, b3, out);
}

// round 3
// speedup vs baseline: 1.0970x; 1.0970x over previous
#include <cuda_runtime.h>
#include <math.h>

#define BATCH   32768
#define KDIM    1280
#define HDIM    64
#define NQ      4
#define NLAYERS 2
#define NCLS    10

#define BM 128
#define BK 16
#define NTHREADS 128
#define KTILES (KDIM / BK)   // 80

#define ASP 132   // As pitch (BM + 4), multiple of 4 for LDS.128 alignment
#define BSP 68    // Bs pitch (HDIM + 4)
#define HSP 68    // Hs pitch

#define PI_HALF 1.57079632679489662f

// smem main: max( double-buffered GEMM tiles, epilogue H tile )
// GEMM: 2*16*132 + 2*16*68 = 6400 floats ; epilogue: 128*68 = 8704 floats
#define SMEM_MAIN_FLOATS 8704
#define AS_BUF (BK * ASP)   // 2112 floats per As buffer
#define BS_BUF (BK * BSP)   // 1088 floats per Bs buffer

__global__ __launch_bounds__(NTHREADS, 2)
void qh_fused_kernel(const float* __restrict__ x,
                     const float* __restrict__ W1,
                     const float* __restrict__ b1,
                     const float* __restrict__ bn_g,
                     const float* __restrict__ bn_b,
                     const float* __restrict__ bn_m,
                     const float* __restrict__ bn_v,
                     const float* __restrict__ W2,
                     const float* __restrict__ b2,
                     const float* __restrict__ qw,
                     const float* __restrict__ W3,
                     const float* __restrict__ b3,
                     float* __restrict__ out)
{
    __shared__ float smem_main[SMEM_MAIN_FLOATS];
    __shared__ float W2s[NQ * HDIM];
    __shared__ float scale_s[HDIM];
    __shared__ float shift_s[HDIM];
    __shared__ float b1s[HDIM];
    __shared__ float qtrig[NLAYERS * NQ * 4];
    __shared__ float W3s[NCLS * NQ];
    __shared__ float b3s[NCLS];
    __shared__ float b2s[NQ];

    const int tid = threadIdx.x;

    // ---- per-block constant prep ----
    if (tid < HDIM) {
        b1s[tid] = b1[tid];
        float sc = bn_g[tid] * rsqrtf(bn_v[tid] + 1e-5f);
        scale_s[tid] = sc;
        shift_s[tid] = bn_b[tid] - bn_m[tid] * sc;
    }
    for (int i = tid; i < NQ * HDIM; i += NTHREADS) W2s[i] = W2[i];
    if (tid < NLAYERS * NQ) {
        float a0 = qw[tid * 2 + 0] * 0.5f;
        float a1 = qw[tid * 2 + 1] * 0.5f;
        qtrig[tid * 4 + 0] = cosf(a0);
        qtrig[tid * 4 + 1] = sinf(a0);
        qtrig[tid * 4 + 2] = cosf(a1);
        qtrig[tid * 4 + 3] = sinf(a1);
    }
    if (tid < NCLS * NQ) W3s[tid] = W3[tid];
    if (tid < NCLS)      b3s[tid] = b3[tid];
    if (tid < NQ)        b2s[tid] = b2[tid];

    // ---- GEMM1: 128x64 tile, 128 threads, 8x8 per thread, double-buffered ----
    float* As = smem_main;                 // [2][BK][ASP], transposed x tile
    float* Bs = smem_main + 2 * AS_BUF;    // [2][BK][BSP], transposed W1 tile

    const int rowBase = blockIdx.x * BM;
    const int ty = tid >> 3;   // 0..15 -> rows ty*8..+7
    const int tx = tid & 7;    // 0..7  -> cols tx*8..+7

    // loader mapping: float4 id = tid + p*128 ; row/h = id>>2, c4 = id&3
    const int lr = tid >> 2;   // 0..31
    const int lc = tid & 3;    // 0..3

    const float* xg = x + (size_t)(rowBase + lr) * KDIM + lc * 4;
    const float* wg = W1 + (size_t)lr * KDIM + lc * 4;

    float4 xa[4], wb[2];

    // prologue: load tile 0
    #pragma unroll
    for (int p = 0; p < 4; ++p) xa[p] = *(const float4*)(xg + (size_t)p * 32 * KDIM);
    #pragma unroll
    for (int p = 0; p < 2; ++p) wb[p] = *(const float4*)(wg + (size_t)p * 32 * KDIM);

    __syncthreads();  // covers constant prep too

    // store tile 0 into buffer 0
    #pragma unroll
    for (int p = 0; p < 4; ++p) {
        const int row = lr + p * 32;
        As[(lc * 4 + 0) * ASP + row] = xa[p].x;
        As[(lc * 4 + 1) * ASP + row] = xa[p].y;
        As[(lc * 4 + 2) * ASP + row] = xa[p].z;
        As[(lc * 4 + 3) * ASP + row] = xa[p].w;
    }
    #pragma unroll
    for (int p = 0; p < 2; ++p) {
        const int h = lr + p * 32;
        Bs[(lc * 4 + 0) * BSP + h] = wb[p].x;
        Bs[(lc * 4 + 1) * BSP + h] = wb[p].y;
        Bs[(lc * 4 + 2) * BSP + h] = wb[p].z;
        Bs[(lc * 4 + 3) * BSP + h] = wb[p].w;
    }
    __syncthreads();

    float acc[8][8];
    #pragma unroll
    for (int i = 0; i < 8; ++i)
        #pragma unroll
        for (int j = 0; j < 8; ++j) acc[i][j] = 0.f;

    for (int kt = 0; kt < KTILES; ++kt) {
        const int cur = kt & 1;

        // prefetch next tile from global
        if (kt < KTILES - 1) {
            const int k0 = (kt + 1) * BK;
            #pragma unroll
            for (int p = 0; p < 4; ++p)
                xa[p] = *(const float4*)(xg + (size_t)p * 32 * KDIM + k0);
            #pragma unroll
            for (int p = 0; p < 2; ++p)
                wb[p] = *(const float4*)(wg + (size_t)p * 32 * KDIM + k0);
        }

        // compute current buffer
        const float* Ac = As + cur * AS_BUF;
        const float* Bc = Bs + cur * BS_BUF;
        #pragma unroll
        for (int k = 0; k < BK; ++k) {
            float4 a0 = *(const float4*)&Ac[k * ASP + ty * 8];
            float4 a1 = *(const float4*)&Ac[k * ASP + ty * 8 + 4];
            float4 b0 = *(const float4*)&Bc[k * BSP + tx * 8];
            float4 b1v = *(const float4*)&Bc[k * BSP + tx * 8 + 4];
            float a[8] = {a0.x, a0.y, a0.z, a0.w, a1.x, a1.y, a1.z, a1.w};
            float b[8] = {b0.x, b0.y, b0.z, b0.w, b1v.x, b1v.y, b1v.z, b1v.w};
            #pragma unroll
            for (int i = 0; i < 8; ++i)
                #pragma unroll
                for (int j = 0; j < 8; ++j)
                    acc[i][j] = fmaf(a[i], b[j], acc[i][j]);
        }

        // store prefetched tile into other buffer
        if (kt < KTILES - 1) {
            float* An = As + (cur ^ 1) * AS_BUF;
            float* Bn = Bs + (cur ^ 1) * BS_BUF;
            #pragma unroll
            for (int p = 0; p < 4; ++p) {
                const int row = lr + p * 32;
                An[(lc * 4 + 0) * ASP + row] = xa[p].x;
                An[(lc * 4 + 1) * ASP + row] = xa[p].y;
                An[(lc * 4 + 2) * ASP + row] = xa[p].z;
                An[(lc * 4 + 3) * ASP + row] = xa[p].w;
            }
            #pragma unroll
            for (int p = 0; p < 2; ++p) {
                const int h = lr + p * 32;
                Bn[(lc * 4 + 0) * BSP + h] = wb[p].x;
                Bn[(lc * 4 + 1) * BSP + h] = wb[p].y;
                Bn[(lc * 4 + 2) * BSP + h] = wb[p].z;
                Bn[(lc * 4 + 3) * BSP + h] = wb[p].w;
            }
            __syncthreads();
        }
    }

    __syncthreads();  // all reads of GEMM buffers done before Hs overwrite

    // ---- epilogue part 1: bias + relu + batchnorm -> Hs ----
    float* Hs = smem_main;  // [BM][HSP]
    #pragma unroll
    for (int i = 0; i < 8; ++i) {
        const int r = ty * 8 + i;
        #pragma unroll
        for (int j = 0; j < 8; ++j) {
            const int h = tx * 8 + j;
            float v = acc[i][j] + b1s[h];
            v = fmaxf(v, 0.f);
            v = v * scale_s[h] + shift_s[h];
            Hs[r * HSP + h] = v;
        }
    }
    __syncthreads();

    // ---- epilogue part 2: one thread per row (128 threads, 128 rows) ----
    {
        const float* hr = &Hs[tid * HSP];

        float xq[NQ];
        #pragma unroll
        for (int q = 0; q < NQ; ++q) {
            float s = b2s[q];
            const float* w2 = &W2s[q * HDIM];
            #pragma unroll
            for (int h = 0; h < HDIM; ++h) s = fmaf(hr[h], w2[h], s);
            xq[q] = tanhf(s);
        }

        float re[16], im[16];
        #pragma unroll
        for (int i = 0; i < 16; ++i) { re[i] = 0.f; im[i] = 0.f; }
        re[0] = 1.f;

        #pragma unroll
        for (int w = 0; w < NQ; ++w) {
            const float half = tanhf(xq[w]) * PI_HALF;
            const float c = cosf(half), s = sinf(half);
            const int st = 8 >> w;
            #pragma unroll
            for (int i = 0; i < 16; ++i) {
                if ((i & st) == 0) {
                    float r0 = re[i],      i0 = im[i];
                    float r1 = re[i + st], i1 = im[i + st];
                    re[i]      = c * r0 - s * r1;
                    im[i]      = c * i0 - s * i1;
                    re[i + st] = s * r0 + c * r1;
                    im[i + st] = s * i0 + c * i1;
                }
            }
        }

        #pragma unroll
        for (int l = 0; l < NLAYERS; ++l) {
            #pragma unroll
            for (int w = 0; w < NQ; ++w) {
                const float cry = qtrig[(l * NQ + w) * 4 + 0];
                const float sry = qtrig[(l * NQ + w) * 4 + 1];
                const float crz = qtrig[(l * NQ + w) * 4 + 2];
                const float srz = qtrig[(l * NQ + w) * 4 + 3];
                const int st = 8 >> w;
                #pragma unroll
                for (int i = 0; i < 16; ++i) {
                    if ((i & st) == 0) {
                        float r0 = re[i],      i0 = im[i];
                        float r1 = re[i + st], i1 = im[i + st];
                        float nr0 = cry * r0 - sry * r1;
                        float ni0 = cry * i0 - sry * i1;
                        float nr1 = sry * r0 + cry * r1;
                        float ni1 = sry * i0 + cry * i1;
                        re[i]      = nr0 * crz + ni0 * srz;
                        im[i]      = ni0 * crz - nr0 * srz;
                        re[i + st] = nr1 * crz - ni1 * srz;
                        im[i + st] = ni1 * crz + nr1 * srz;
                    }
                }
            }
            #pragma unroll
            for (int w = 0; w < NQ; ++w) {
                const int cs = 8 >> w;
                const int ts = 8 >> ((w + 1) & 3);
                #pragma unroll
                for (int i = 0; i < 16; ++i) {
                    if ((i & cs) != 0 && (i & ts) == 0) {
                        float tr = re[i]; re[i] = re[i + ts]; re[i + ts] = tr;
                        float ti = im[i]; im[i] = im[i + ts]; im[i + ts] = ti;
                    }
                }
            }
        }

        float z[NQ] = {0.f, 0.f, 0.f, 0.f};
        #pragma unroll
        for (int i = 0; i < 16; ++i) {
            const float p = re[i] * re[i] + im[i] * im[i];
            #pragma unroll
            for (int w = 0; w < NQ; ++w)
                z[w] += ((i >> (3 - w)) & 1) ? -p : p;
        }

        const int r = rowBase + tid;
        #pragma unroll
        for (int c = 0; c < NCLS; ++c) {
            float s = b3s[c];
            #pragma unroll
            for (int q = 0; q < NQ; ++q) s = fmaf(z[q], W3s[c * NQ + q], s);
            out[r * NCLS + c] = s;
        }
    }
}

extern "C" void kernel_launch(void* const* d_in, const int* in_sizes, int n_in,
                              void* d_out, int out_size)
{
    const float* x    = (const float*)d_in[0];
    const float* W1   = (const float*)d_in[1];
    const float* b1   = (const float*)d_in[2];
    const float* bn_g = (const float*)d_in[3];
    const float* bn_b = (const float*)d_in[4];
    const float* bn_m = (const float*)d_in[5];
    const float* bn_v = (const float*)d_in[6];
    const float* W2   = (const float*)d_in[7];
    const float* b2   = (const float*)d_in[8];
    const float* qw   = (const float*)d_in[9];
    const float* W3   = (const float*)d_in[10];
    const float* b3   = (const float*)d_in[11];
    float* out = (float*)d_out;

    dim3 grid(BATCH / BM);
    dim3 block(NTHREADS);
    qh_fused_kernel<<<grid, block>>>(x, W1, b1, bn_g, bn_b, bn_m, bn_v,
                                     W2, b2, qw, W3, b3, out);
}

// round 4
// speedup vs baseline: 1.0998x; 1.0025x over previous
#include <cuda_runtime.h>
#include <math.h>

#define BATCH   32768
#define KDIM    1280
#define HDIM    64
#define NQ      4
#define NLAYERS 2
#define NCLS    10

#define BM 128
#define BK 16
#define NTHREADS 128
#define KTILES (KDIM / BK)   // 80

#define ASP 132   // As pitch (BM + 4), multiple of 4 for LDS.128 alignment
#define BSP 68    // Bs pitch (HDIM + 4)
#define HSP 68    // Hs pitch

#define PI_HALF 1.57079632679489662f

// smem main: max( double-buffered GEMM tiles, epilogue H tile )
// GEMM: 2*16*132 + 2*16*68 = 6400 floats ; epilogue: 128*68 = 8704 floats
#define SMEM_MAIN_FLOATS 8704
#define AS_BUF (BK * ASP)   // 2112 floats per As buffer
#define BS_BUF (BK * BSP)   // 1088 floats per Bs buffer

__global__ __launch_bounds__(NTHREADS, 2)
void qh_fused_kernel(const float* __restrict__ x,
                     const float* __restrict__ W1,
                     const float* __restrict__ b1,
                     const float* __restrict__ bn_g,
                     const float* __restrict__ bn_b,
                     const float* __restrict__ bn_m,
                     const float* __restrict__ bn_v,
                     const float* __restrict__ W2,
                     const float* __restrict__ b2,
                     const float* __restrict__ qw,
                     const float* __restrict__ W3,
                     const float* __restrict__ b3,
                     float* __restrict__ out)
{
    __shared__ float smem_main[SMEM_MAIN_FLOATS];
    __shared__ float W2s[NQ * HDIM];
    __shared__ float scale_s[HDIM];
    __shared__ float shift_s[HDIM];
    __shared__ float b1s[HDIM];
    __shared__ float qtrig[NLAYERS * NQ * 4];
    __shared__ float W3s[NCLS * NQ];
    __shared__ float b3s[NCLS];
    __shared__ float b2s[NQ];

    const int tid = threadIdx.x;

    // ---- per-block constant prep ----
    if (tid < HDIM) {
        b1s[tid] = b1[tid];
        float sc = bn_g[tid] * rsqrtf(bn_v[tid] + 1e-5f);
        scale_s[tid] = sc;
        shift_s[tid] = bn_b[tid] - bn_m[tid] * sc;
    }
    for (int i = tid; i < NQ * HDIM; i += NTHREADS) W2s[i] = W2[i];
    if (tid < NLAYERS * NQ) {
        float a0 = qw[tid * 2 + 0] * 0.5f;
        float a1 = qw[tid * 2 + 1] * 0.5f;
        qtrig[tid * 4 + 0] = cosf(a0);
        qtrig[tid * 4 + 1] = sinf(a0);
        qtrig[tid * 4 + 2] = cosf(a1);
        qtrig[tid * 4 + 3] = sinf(a1);
    }
    if (tid < NCLS * NQ) W3s[tid] = W3[tid];
    if (tid < NCLS)      b3s[tid] = b3[tid];
    if (tid < NQ)        b2s[tid] = b2[tid];

    // ---- GEMM1: 128x64 tile, 128 threads, 8x8 per thread, double-buffered ----
    float* As = smem_main;                 // [2][BK][ASP], transposed x tile
    float* Bs = smem_main + 2 * AS_BUF;    // [2][BK][BSP], transposed W1 tile

    const int rowBase = blockIdx.x * BM;
    const int ty = tid >> 3;   // 0..15 -> rows ty*8..+7
    const int tx = tid & 7;    // 0..7  -> cols tx*8..+7

    // loader mapping: float4 id = tid + p*128 ; row/h = id>>2, c4 = id&3
    const int lr = tid >> 2;   // 0..31
    const int lc = tid & 3;    // 0..3

    const float* xg = x + (size_t)(rowBase + lr) * KDIM + lc * 4;
    const float* wg = W1 + (size_t)lr * KDIM + lc * 4;

    float4 xa[4], wb[2];

    // prologue: load tile 0
    #pragma unroll
    for (int p = 0; p < 4; ++p) xa[p] = *(const float4*)(xg + (size_t)p * 32 * KDIM);
    #pragma unroll
    for (int p = 0; p < 2; ++p) wb[p] = *(const float4*)(wg + (size_t)p * 32 * KDIM);

    __syncthreads();  // covers constant prep too

    // store tile 0 into buffer 0
    #pragma unroll
    for (int p = 0; p < 4; ++p) {
        const int row = lr + p * 32;
        As[(lc * 4 + 0) * ASP + row] = xa[p].x;
        As[(lc * 4 + 1) * ASP + row] = xa[p].y;
        As[(lc * 4 + 2) * ASP + row] = xa[p].z;
        As[(lc * 4 + 3) * ASP + row] = xa[p].w;
    }
    #pragma unroll
    for (int p = 0; p < 2; ++p) {
        const int h = lr + p * 32;
        Bs[(lc * 4 + 0) * BSP + h] = wb[p].x;
        Bs[(lc * 4 + 1) * BSP + h] = wb[p].y;
        Bs[(lc * 4 + 2) * BSP + h] = wb[p].z;
        Bs[(lc * 4 + 3) * BSP + h] = wb[p].w;
    }
    __syncthreads();

    float acc[8][8];
    #pragma unroll
    for (int i = 0; i < 8; ++i)
        #pragma unroll
        for (int j = 0; j < 8; ++j) acc[i][j] = 0.f;

    for (int kt = 0; kt < KTILES; ++kt) {
        const int cur = kt & 1;

        // prefetch next tile from global
        if (kt < KTILES - 1) {
            const int k0 = (kt + 1) * BK;
            #pragma unroll
            for (int p = 0; p < 4; ++p)
                xa[p] = *(const float4*)(xg + (size_t)p * 32 * KDIM + k0);
            #pragma unroll
            for (int p = 0; p < 2; ++p)
                wb[p] = *(const float4*)(wg + (size_t)p * 32 * KDIM + k0);
        }

        // compute current buffer
        const float* Ac = As + cur * AS_BUF;
        const float* Bc = Bs + cur * BS_BUF;
        #pragma unroll
        for (int k = 0; k < BK; ++k) {
            float4 a0 = *(const float4*)&Ac[k * ASP + ty * 8];
            float4 a1 = *(const float4*)&Ac[k * ASP + ty * 8 + 4];
            float4 b0 = *(const float4*)&Bc[k * BSP + tx * 8];
            float4 b1v = *(const float4*)&Bc[k * BSP + tx * 8 + 4];
            float a[8] = {a0.x, a0.y, a0.z, a0.w, a1.x, a1.y, a1.z, a1.w};
            float b[8] = {b0.x, b0.y, b0.z, b0.w, b1v.x, b1v.y, b1v.z, b1v.w};
            #pragma unroll
            for (int i = 0; i < 8; ++i)
                #pragma unroll
                for (int j = 0; j < 8; ++j)
                    acc[i][j] = fmaf(a[i], b[j], acc[i][j]);
        }

        // store prefetched tile into other buffer
        if (kt < KTILES - 1) {
            float* An = As + (cur ^ 1) * AS_BUF;
            float* Bn = Bs + (cur ^ 1) * BS_BUF;
            #pragma unroll
            for (int p = 0; p < 4; ++p) {
                const int row = lr + p * 32;
                An[(lc * 4 + 0) * ASP + row] = xa[p].x;
                An[(lc * 4 + 1) * ASP + row] = xa[p].y;
                An[(lc * 4 + 2) * ASP + row] = xa[p].z;
                An[(lc * 4 + 3) * ASP + row] = xa[p].w;
            }
            #pragma unroll
            for (int p = 0; p < 2; ++p) {
                const int h = lr + p * 32;
                Bn[(lc * 4 + 0) * BSP + h] = wb[p].x;
                Bn[(lc * 4 + 1) * BSP + h] = wb[p].y;
                Bn[(lc * 4 + 2) * BSP + h] = wb[p].z;
                Bn[(lc * 4 + 3) * BSP + h] = wb[p].w;
            }
            __syncthreads();
        }
    }

    __syncthreads();  // all reads of GEMM buffers done before Hs overwrite

    // ---- epilogue part 1: bias + relu + batchnorm -> Hs ----
    float* Hs = smem_main;  // [BM][HSP]
    #pragma unroll
    for (int i = 0; i < 8; ++i) {
        const int r = ty * 8 + i;
        #pragma unroll
        for (int j = 0; j < 8; ++j) {
            const int h = tx * 8 + j;
            float v = acc[i][j] + b1s[h];
            v = fmaxf(v, 0.f);
            v = v * scale_s[h] + shift_s[h];
            Hs[r * HSP + h] = v;
        }
    }
    __syncthreads();

    // ---- epilogue part 2: one thread per row (128 threads, 128 rows) ----
    {
        const float* hr = &Hs[tid * HSP];

        float xq[NQ];
        #pragma unroll
        for (int q = 0; q < NQ; ++q) {
            float s = b2s[q];
            const float* w2 = &W2s[q * HDIM];
            #pragma unroll
            for (int h = 0; h < HDIM; ++h) s = fmaf(hr[h], w2[h], s);
            xq[q] = tanhf(s);
        }

        float re[16], im[16];
        #pragma unroll
        for (int i = 0; i < 16; ++i) { re[i] = 0.f; im[i] = 0.f; }
        re[0] = 1.f;

        #pragma unroll
        for (int w = 0; w < NQ; ++w) {
            const float half = tanhf(xq[w]) * PI_HALF;
            const float c = cosf(half), s = sinf(half);
            const int st = 8 >> w;
            #pragma unroll
            for (int i = 0; i < 16; ++i) {
                if ((i & st) == 0) {
                    float r0 = re[i],      i0 = im[i];
                    float r1 = re[i + st], i1 = im[i + st];
                    re[i]      = c * r0 - s * r1;
                    im[i]      = c * i0 - s * i1;
                    re[i + st] = s * r0 + c * r1;
                    im[i + st] = s * i0 + c * i1;
                }
            }
        }

        #pragma unroll
        for (int l = 0; l < NLAYERS; ++l) {
            #pragma unroll
            for (int w = 0; w < NQ; ++w) {
                const float cry = qtrig[(l * NQ + w) * 4 + 0];
                const float sry = qtrig[(l * NQ + w) * 4 + 1];
                const float crz = qtrig[(l * NQ + w) * 4 + 2];
                const float srz = qtrig[(l * NQ + w) * 4 + 3];
                const int st = 8 >> w;
                #pragma unroll
                for (int i = 0; i < 16; ++i) {
                    if ((i & st) == 0) {
                        float r0 = re[i],      i0 = im[i];
                        float r1 = re[i + st], i1 = im[i + st];
                        float nr0 = cry * r0 - sry * r1;
                        float ni0 = cry * i0 - sry * i1;
                        float nr1 = sry * r0 + cry * r1;
                        float ni1 = sry * i0 + cry * i1;
                        re[i]      = nr0 * crz + ni0 * srz;
                        im[i]      = ni0 * crz - nr0 * srz;
                        re[i + st] = nr1 * crz - ni1 * srz;
                        im[i + st] = ni1 * crz + nr1 * srz;
                    }
                }
            }
            #pragma unroll
            for (int w = 0; w < NQ; ++w) {
                const int cs = 8 >> w;
                const int ts = 8 >> ((w + 1) & 3);
                #pragma unroll
                for (int i = 0; i < 16; ++i) {
                    if ((i & cs) != 0 && (i & ts) == 0) {
                        float tr = re[i]; re[i] = re[i + ts]; re[i + ts] = tr;
                        float ti = im[i]; im[i] = im[i + ts]; im[i + ts] = ti;
                    }
                }
            }
        }

        float z[NQ] = {0.f, 0.f, 0.f, 0.f};
        #pragma unroll
        for (int i = 0; i < 16; ++i) {
            const float p = re[i] * re[i] + im[i] * im[i];
            #pragma unroll
            for (int w = 0; w < NQ; ++w)
                z[w] += ((i >> (3 - w)) & 1) ? -p : p;
        }

        const int r = rowBase + tid;
        #pragma unroll
        for (int c = 0; c < NCLS; ++c) {
            float s = b3s[c];
            #pragma unroll
            for (int q = 0; q < NQ; ++q) s = fmaf(z[q], W3s[c * NQ + q], s);
            out[r * NCLS + c] = s;
        }
    }
}

extern "C" void kernel_launch(void* const* d_in, const int* in_sizes, int n_in,
                              void* d_out, int out_size)
{
    const float* x    = (const float*)d_in[0];
    const float* W1   = (const float*)d_in[1];
    const float* b1   = (const float*)d_in[2];
    const float* bn_g = (const float*)d_in[3];
    const float* bn_b = (const float*)d_in[4];
    const float* bn_m = (const float*)d_in[5];
    const float* bn_v = (const float*)d_in[6];
    const float* W2   = (const float*)d_in[7];
    const float* b2   = (const float*)d_in[8];
    const float* qw   = (const float*)d_in[9];
    const float* W3   = (const float*)d_in[10];
    const float* b3   = (const float*)d_in[11];
    float* out = (float*)d_out;

    dim3 grid(BATCH / BM);
    dim3 block(NTHREADS);
    qh_fused_kernel<<<grid, block>>>(x, W1, b1, bn_g, bn_b, bn_m, bn_v,
                                     W2, b2, qw, W3, b3, out);
}

// round 8
// speedup vs baseline: 2.7518x; 2.5022x over previous
#include <cuda_runtime.h>
#include <math.h>
#include <stdint.h>

#define BATCH   32768
#define KDIM    1280
#define HDIM    64
#define NQ      4
#define NLAYERS 2
#define NCLS    10

#define BM       128
#define BKF      32                 // fp32 K elements per stage (= 2 k16 chunks)
#define NSTAGES  (KDIM / BKF)       // 40
#define NTHREADS 256
#define PI_HALF  1.57079632679489662f

// stage layout (bytes): A_hi[128x32 bf16]=8192, A_lo=8192, B_hi[64x32]=4096, B_lo=4096
#define A_HI 0
#define A_LO 8192
#define B_HI 16384
#define B_LO 20480
#define STAGE 24576
#define DSMEM_BYTES (2 * STAGE)     // 48 KB (opt-in via cudaFuncSetAttribute)

// ---------------- helpers ----------------
__device__ __forceinline__ uint32_t smem_u32(const void* p) {
    uint32_t a;
    asm("{ .reg .u64 t; cvta.to.shared.u64 t, %1; cvt.u32.u64 %0, t; }"
        : "=r"(a) : "l"(p));
    return a;
}
__device__ __forceinline__ void sts128(uint32_t a, uint32_t x, uint32_t y,
                                       uint32_t z, uint32_t w) {
    asm volatile("st.shared.v4.b32 [%0], {%1,%2,%3,%4};"
                 :: "r"(a), "r"(x), "r"(y), "r"(z), "r"(w) : "memory");
}
__device__ __forceinline__ uint32_t prmt_hi(float a, float b) {
    uint32_t r;
    asm("prmt.b32 %0, %1, %2, 0x7632;"
        : "=r"(r) : "r"(__float_as_uint(a)), "r"(__float_as_uint(b)));
    return r;
}
__device__ __forceinline__ float resid(float v) {
    return v - __uint_as_float(__float_as_uint(v) & 0xffff0000u);
}
__device__ __forceinline__ uint32_t pack_bf16(float lo, float hi) {
    uint32_t r;
    asm("cvt.rn.bf16x2.f32 %0, %1, %2;" : "=r"(r) : "f"(hi), "f"(lo));
    return r;
}
__device__ __forceinline__ void ldsm4(uint32_t r[4], uint32_t addr) {
    asm volatile("ldmatrix.sync.aligned.m8n8.x4.shared.b16 {%0,%1,%2,%3}, [%4];"
                 : "=r"(r[0]), "=r"(r[1]), "=r"(r[2]), "=r"(r[3]) : "r"(addr));
}
__device__ __forceinline__ void mma_bf16(float* d, const uint32_t* a,
                                         const uint32_t* b) {
    asm volatile("mma.sync.aligned.m16n8k16.row.col.f32.bf16.bf16.f32 "
                 "{%0,%1,%2,%3}, {%4,%5,%6,%7}, {%8,%9}, {%0,%1,%2,%3};"
                 : "+f"(d[0]), "+f"(d[1]), "+f"(d[2]), "+f"(d[3])
                 : "r"(a[0]), "r"(a[1]), "r"(a[2]), "r"(a[3]),
                   "r"(b[0]), "r"(b[1]));
}
// convert 8 fp32 (two float4) -> hi/lo bf16 16B chunks
__device__ __forceinline__ void cvt_store(uint32_t hi_a, uint32_t lo_a,
                                          float4 f0, float4 f1) {
    sts128(hi_a, prmt_hi(f0.x, f0.y), prmt_hi(f0.z, f0.w),
                 prmt_hi(f1.x, f1.y), prmt_hi(f1.z, f1.w));
    sts128(lo_a, pack_bf16(resid(f0.x), resid(f0.y)),
                 pack_bf16(resid(f0.z), resid(f0.w)),
                 pack_bf16(resid(f1.x), resid(f1.y)),
                 pack_bf16(resid(f1.z), resid(f1.w)));
}
// swizzled byte offset within a plane: row pitch 64B, 4x16B chunks
__device__ __forceinline__ uint32_t swz(int row, int ch) {
    return (uint32_t)(row * 64 + ((ch ^ ((row >> 1) & 3)) << 4));
}

__global__ __launch_bounds__(NTHREADS, 2)
void qh_mma_kernel(const float* __restrict__ x,
                   const float* __restrict__ W1,
                   const float* __restrict__ b1,
                   const float* __restrict__ bn_g,
                   const float* __restrict__ bn_b,
                   const float* __restrict__ bn_m,
                   const float* __restrict__ bn_v,
                   const float* __restrict__ W2,
                   const float* __restrict__ b2,
                   const float* __restrict__ qw,
                   const float* __restrict__ W3,
                   const float* __restrict__ b3,
                   float* __restrict__ out)
{
    extern __shared__ char dsmem_raw[];
    const uint32_t tile_base = smem_u32(dsmem_raw);

    __shared__ float W2s[NQ * HDIM];
    __shared__ float scale_s[HDIM], shift_s[HDIM], b1s[HDIM];
    __shared__ float qtrig[NLAYERS * NQ * 4];
    __shared__ float W3s[NCLS * NQ], b3s[NCLS], b2s[NQ];

    const int tid = threadIdx.x;
    const int wid = tid >> 5;
    const int lane = tid & 31;
    const int rowBase = blockIdx.x * BM;

    // ---- constants ----
    if (tid < HDIM) {
        b1s[tid] = b1[tid];
        float sc = bn_g[tid] * rsqrtf(bn_v[tid] + 1e-5f);
        scale_s[tid] = sc;
        shift_s[tid] = bn_b[tid] - bn_m[tid] * sc;
    }
    for (int i = tid; i < NQ * HDIM; i += NTHREADS) W2s[i] = W2[i];
    if (tid < NLAYERS * NQ) {
        float a0 = qw[tid * 2 + 0] * 0.5f, a1 = qw[tid * 2 + 1] * 0.5f;
        qtrig[tid * 4 + 0] = cosf(a0); qtrig[tid * 4 + 1] = sinf(a0);
        qtrig[tid * 4 + 2] = cosf(a1); qtrig[tid * 4 + 3] = sinf(a1);
    }
    if (tid < NCLS * NQ) W3s[tid] = W3[tid];
    if (tid < NCLS)      b3s[tid] = b3[tid];
    if (tid < NQ)        b2s[tid] = b2[tid];

    // ---- warp tiling: 4(m) x 2(n); warp = 32x32 ----
    const int m0 = (wid & 3) * 32;
    const int n0 = (wid >> 2) * 32;

    // ldmatrix per-lane address components
    const int li = lane >> 3;      // 8-lane group 0..3
    const int lrow = lane & 7;
    // A: group i -> rows (i&1)*8, chunk-in-k16 = i>>1
    const int r0A = m0 + ((li & 1) << 3) + lrow;
    const uint32_t aLane = (uint32_t)(r0A * 64);
    const uint32_t xrA = (uint32_t)((r0A >> 1) & 3);
    const uint32_t ciA = (uint32_t)(li >> 1);
    // B: group i -> rows (i>>1)*8, chunk = i&1
    const int r0B = n0 + ((li >> 1) << 3) + lrow;
    const uint32_t bLane = (uint32_t)(r0B * 64);
    const uint32_t xrB = (uint32_t)((r0B >> 1) & 3);
    const uint32_t ciB = (uint32_t)(li & 1);

    // ---- loader mapping ----
    // x: 512 chunks/stage (128 rows x 4); thread owns chunks tid, tid+256
    const int xr1 = tid >> 2,        xc1 = tid & 3;
    const int xr2 = 64 + (tid >> 2), xc2 = tid & 3;
    const float* xp1 = x + (size_t)(rowBase + xr1) * KDIM + xc1 * 8;
    const float* xp2 = x + (size_t)(rowBase + xr2) * KDIM + xc2 * 8;
    const uint32_t xs1 = swz(xr1, xc1), xs2 = swz(xr2, xc2);
    // W1: 256 chunks/stage (64 rows x 4); thread owns chunk tid
    const int wr = tid >> 2, wc = tid & 3;
    const float* wp = W1 + (size_t)wr * KDIM + wc * 8;
    const uint32_t ws = swz(wr, wc);

    float4 xf1a, xf1b, xf2a, xf2b, wfa, wfb;

    // prologue: load + convert stage 0 into buffer 0
    xf1a = *(const float4*)(xp1);     xf1b = *(const float4*)(xp1 + 4);
    xf2a = *(const float4*)(xp2);     xf2b = *(const float4*)(xp2 + 4);
    wfa  = *(const float4*)(wp);      wfb  = *(const float4*)(wp + 4);
    cvt_store(tile_base + A_HI + xs1, tile_base + A_LO + xs1, xf1a, xf1b);
    cvt_store(tile_base + A_HI + xs2, tile_base + A_LO + xs2, xf2a, xf2b);
    cvt_store(tile_base + B_HI + ws,  tile_base + B_LO + ws,  wfa,  wfb);
    __syncthreads();

    float acc[2][4][4];
    #pragma unroll
    for (int mt = 0; mt < 2; ++mt)
        #pragma unroll
        for (int t = 0; t < 4; ++t)
            #pragma unroll
            for (int e = 0; e < 4; ++e) acc[mt][t][e] = 0.f;

    for (int s = 0; s < NSTAGES; ++s) {
        const uint32_t ab = tile_base + (uint32_t)((s & 1) * STAGE);

        // prefetch stage s+1
        if (s < NSTAGES - 1) {
            const int ko = (s + 1) * BKF;
            xf1a = *(const float4*)(xp1 + ko); xf1b = *(const float4*)(xp1 + ko + 4);
            xf2a = *(const float4*)(xp2 + ko); xf2b = *(const float4*)(xp2 + ko + 4);
            wfa  = *(const float4*)(wp + ko);  wfb  = *(const float4*)(wp + ko + 4);
        }

        // compute 2 k16 chunks of current buffer
        #pragma unroll
        for (int kt = 0; kt < 2; ++kt) {
            const uint32_t aoff = (uint32_t)((((2 * kt + ciA) ^ xrA)) << 4);
            const uint32_t boff = (uint32_t)((((2 * kt + ciB) ^ xrB)) << 4);
            uint32_t ahi[2][4], alo[2][4], bhi[2][4], blo[2][4];
            #pragma unroll
            for (int mt = 0; mt < 2; ++mt) {
                ldsm4(ahi[mt], ab + A_HI + aLane + mt * 1024 + aoff);
                ldsm4(alo[mt], ab + A_LO + aLane + mt * 1024 + aoff);
            }
            #pragma unroll
            for (int j = 0; j < 2; ++j) {
                ldsm4(bhi[j], ab + B_HI + bLane + j * 1024 + boff);
                ldsm4(blo[j], ab + B_LO + bLane + j * 1024 + boff);
            }
            #pragma unroll
            for (int mt = 0; mt < 2; ++mt)
                #pragma unroll
                for (int t = 0; t < 4; ++t) {
                    const uint32_t* bh = &bhi[t >> 1][(t & 1) * 2];
                    const uint32_t* bl = &blo[t >> 1][(t & 1) * 2];
                    mma_bf16(acc[mt][t], ahi[mt], bh);
                    mma_bf16(acc[mt][t], ahi[mt], bl);
                    mma_bf16(acc[mt][t], alo[mt], bh);
                }
        }

        // store stage s+1 into other buffer
        if (s < NSTAGES - 1) {
            const uint32_t nb = tile_base + (uint32_t)(((s + 1) & 1) * STAGE);
            cvt_store(nb + A_HI + xs1, nb + A_LO + xs1, xf1a, xf1b);
            cvt_store(nb + A_HI + xs2, nb + A_LO + xs2, xf2a, xf2b);
            cvt_store(nb + B_HI + ws,  nb + B_LO + ws,  wfa,  wfb);
        }
        __syncthreads();
    }

    // ---- epilogue part 1: bias+relu+bn -> Hs (overlays GEMM buffers) ----
    float* Hs = (float*)dsmem_raw;   // [128][65]
    {
        const int rr = lane >> 2;
        const int cc = (lane & 3) * 2;
        #pragma unroll
        for (int mt = 0; mt < 2; ++mt)
            #pragma unroll
            for (int t = 0; t < 4; ++t) {
                const int row = m0 + mt * 16 + rr;
                const int col = n0 + t * 8 + cc;
                float v0 = fmaxf(acc[mt][t][0] + b1s[col], 0.f)     * scale_s[col]     + shift_s[col];
                float v1 = fmaxf(acc[mt][t][1] + b1s[col + 1], 0.f) * scale_s[col + 1] + shift_s[col + 1];
                float v2 = fmaxf(acc[mt][t][2] + b1s[col], 0.f)     * scale_s[col]     + shift_s[col];
                float v3 = fmaxf(acc[mt][t][3] + b1s[col + 1], 0.f) * scale_s[col + 1] + shift_s[col + 1];
                Hs[row * 65 + col]           = v0;
                Hs[row * 65 + col + 1]       = v1;
                Hs[(row + 8) * 65 + col]     = v2;
                Hs[(row + 8) * 65 + col + 1] = v3;
            }
    }
    __syncthreads();

    // ---- epilogue part 2: quantum circuit, one thread per row ----
    if (tid < BM) {
        const float* hr = &Hs[tid * 65];

        float xqa[NQ] = {b2s[0], b2s[1], b2s[2], b2s[3]};
        #pragma unroll
        for (int h = 0; h < HDIM; ++h) {
            const float v = hr[h];
            #pragma unroll
            for (int q = 0; q < NQ; ++q)
                xqa[q] = fmaf(v, W2s[q * HDIM + h], xqa[q]);
        }

        float re[16], im[16];
        #pragma unroll
        for (int i = 0; i < 16; ++i) { re[i] = 0.f; im[i] = 0.f; }
        re[0] = 1.f;

        // encoder: angle = tanh(tanh(pre)) * pi, RY half-angle
        #pragma unroll
        for (int w = 0; w < NQ; ++w) {
            const float half_a = tanhf(tanhf(xqa[w])) * PI_HALF;
            const float c = cosf(half_a), s = sinf(half_a);
            const int st = 8 >> w;
            #pragma unroll
            for (int i = 0; i < 16; ++i) {
                if ((i & st) == 0) {
                    float r0 = re[i], i0 = im[i];
                    float r1 = re[i + st], i1 = im[i + st];
                    re[i]      = c * r0 - s * r1;
                    im[i]      = c * i0 - s * i1;
                    re[i + st] = s * r0 + c * r1;
                    im[i + st] = s * i0 + c * i1;
                }
            }
        }

        #pragma unroll
        for (int l = 0; l < NLAYERS; ++l) {
            #pragma unroll
            for (int w = 0; w < NQ; ++w) {
                const float cry = qtrig[(l * NQ + w) * 4 + 0];
                const float sry = qtrig[(l * NQ + w) * 4 + 1];
                const float crz = qtrig[(l * NQ + w) * 4 + 2];
                const float srz = qtrig[(l * NQ + w) * 4 + 3];
                const int st = 8 >> w;
                #pragma unroll
                for (int i = 0; i < 16; ++i) {
                    if ((i & st) == 0) {
                        float r0 = re[i], i0 = im[i];
                        float r1 = re[i + st], i1 = im[i + st];
                        float nr0 = cry * r0 - sry * r1;
                        float ni0 = cry * i0 - sry * i1;
                        float nr1 = sry * r0 + cry * r1;
                        float ni1 = sry * i0 + cry * i1;
                        re[i]      = nr0 * crz + ni0 * srz;
                        im[i]      = ni0 * crz - nr0 * srz;
                        re[i + st] = nr1 * crz - ni1 * srz;
                        im[i + st] = ni1 * crz + nr1 * srz;
                    }
                }
            }
            #pragma unroll
            for (int w = 0; w < NQ; ++w) {
                const int cs = 8 >> w;
                const int ts = 8 >> ((w + 1) & 3);
                #pragma unroll
                for (int i = 0; i < 16; ++i) {
                    if ((i & cs) != 0 && (i & ts) == 0) {
                        float tr = re[i]; re[i] = re[i + ts]; re[i + ts] = tr;
                        float ti = im[i]; im[i] = im[i + ts]; im[i + ts] = ti;
                    }
                }
            }
        }

        float z[NQ] = {0.f, 0.f, 0.f, 0.f};
        #pragma unroll
        for (int i = 0; i < 16; ++i) {
            const float p = re[i] * re[i] + im[i] * im[i];
            #pragma unroll
            for (int w = 0; w < NQ; ++w)
                z[w] += ((i >> (3 - w)) & 1) ? -p : p;
        }

        const int r = rowBase + tid;
        #pragma unroll
        for (int c = 0; c < NCLS; ++c) {
            float sv = b3s[c];
            #pragma unroll
            for (int q = 0; q < NQ; ++q) sv = fmaf(z[q], W3s[c * NQ + q], sv);
            out[r * NCLS + c] = sv;
        }
    }
}

extern "C" void kernel_launch(void* const* d_in, const int* in_sizes, int n_in,
                              void* d_out, int out_size)
{
    const float* x    = (const float*)d_in[0];
    const float* W1   = (const float*)d_in[1];
    const float* b1   = (const float*)d_in[2];
    const float* bn_g = (const float*)d_in[3];
    const float* bn_b = (const float*)d_in[4];
    const float* bn_m = (const float*)d_in[5];
    const float* bn_v = (const float*)d_in[6];
    const float* W2   = (const float*)d_in[7];
    const float* b2   = (const float*)d_in[8];
    const float* qw   = (const float*)d_in[9];
    const float* W3   = (const float*)d_in[10];
    const float* b3   = (const float*)d_in[11];
    float* out = (float*)d_out;

    // dynamic 48KB + ~2.4KB static shared exceeds the 48KB default cap:
    // opt in to a larger dynamic-smem limit (host-side attribute, not a
    // stream op — legal under graph capture, creates no graph nodes).
    cudaFuncSetAttribute(qh_mma_kernel,
                         cudaFuncAttributeMaxDynamicSharedMemorySize, DSMEM_BYTES);

    dim3 grid(BATCH / BM);
    dim3 block(NTHREADS);
    qh_mma_kernel<<<grid, block, DSMEM_BYTES>>>(x, W1, b1, bn_g, bn_b, bn_m, bn_v,
                                                W2, b2, qw, W3, b3, out);
}

// round 9
// speedup vs baseline: 2.7586x; 1.0024x over previous
#include <cuda_runtime.h>
#include <math.h>
#include <stdint.h>

#define BATCH   32768
#define KDIM    1280
#define HDIM    64
#define NQ      4
#define NLAYERS 2
#define NCLS    10

#define BM       128
#define BKF      32                 // fp32 K elements per stage (= 2 k16 chunks)
#define NSTAGES  (KDIM / BKF)       // 40
#define NTHREADS 256
#define PI_HALF  1.57079632679489662f

// stage layout (bytes): A_hi[128x32 bf16]=8192, A_lo=8192, B_hi[64x32]=4096, B_lo=4096
#define A_HI 0
#define A_LO 8192
#define B_HI 16384
#define B_LO 20480
#define STAGE 24576
#define DSMEM_BYTES (2 * STAGE)     // 48 KB (opt-in via cudaFuncSetAttribute)

// ---------------- helpers ----------------
__device__ __forceinline__ uint32_t smem_u32(const void* p) {
    uint32_t a;
    asm("{ .reg .u64 t; cvta.to.shared.u64 t, %1; cvt.u32.u64 %0, t; }"
        : "=r"(a) : "l"(p));
    return a;
}
__device__ __forceinline__ void sts128(uint32_t a, uint32_t x, uint32_t y,
                                       uint32_t z, uint32_t w) {
    asm volatile("st.shared.v4.b32 [%0], {%1,%2,%3,%4};"
                 :: "r"(a), "r"(x), "r"(y), "r"(z), "r"(w) : "memory");
}
__device__ __forceinline__ uint32_t prmt_hi(float a, float b) {
    uint32_t r;
    asm("prmt.b32 %0, %1, %2, 0x7632;"
        : "=r"(r) : "r"(__float_as_uint(a)), "r"(__float_as_uint(b)));
    return r;
}
__device__ __forceinline__ float resid(float v) {
    return v - __uint_as_float(__float_as_uint(v) & 0xffff0000u);
}
__device__ __forceinline__ uint32_t pack_bf16(float lo, float hi) {
    uint32_t r;
    asm("cvt.rn.bf16x2.f32 %0, %1, %2;" : "=r"(r) : "f"(hi), "f"(lo));
    return r;
}
__device__ __forceinline__ void ldsm4(uint32_t r[4], uint32_t addr) {
    asm volatile("ldmatrix.sync.aligned.m8n8.x4.shared.b16 {%0,%1,%2,%3}, [%4];"
                 : "=r"(r[0]), "=r"(r[1]), "=r"(r[2]), "=r"(r[3]) : "r"(addr));
}
__device__ __forceinline__ void mma_bf16(float* d, const uint32_t* a,
                                         const uint32_t* b) {
    asm volatile("mma.sync.aligned.m16n8k16.row.col.f32.bf16.bf16.f32 "
                 "{%0,%1,%2,%3}, {%4,%5,%6,%7}, {%8,%9}, {%0,%1,%2,%3};"
                 : "+f"(d[0]), "+f"(d[1]), "+f"(d[2]), "+f"(d[3])
                 : "r"(a[0]), "r"(a[1]), "r"(a[2]), "r"(a[3]),
                   "r"(b[0]), "r"(b[1]));
}
// convert 8 fp32 (two float4) -> hi/lo bf16 16B chunks
__device__ __forceinline__ void cvt_store(uint32_t hi_a, uint32_t lo_a,
                                          float4 f0, float4 f1) {
    sts128(hi_a, prmt_hi(f0.x, f0.y), prmt_hi(f0.z, f0.w),
                 prmt_hi(f1.x, f1.y), prmt_hi(f1.z, f1.w));
    sts128(lo_a, pack_bf16(resid(f0.x), resid(f0.y)),
                 pack_bf16(resid(f0.z), resid(f0.w)),
                 pack_bf16(resid(f1.x), resid(f1.y)),
                 pack_bf16(resid(f1.z), resid(f1.w)));
}
// swizzled byte offset within a plane: row pitch 64B, 4x16B chunks
__device__ __forceinline__ uint32_t swz(int row, int ch) {
    return (uint32_t)(row * 64 + ((ch ^ ((row >> 1) & 3)) << 4));
}

__global__ __launch_bounds__(NTHREADS, 2)
void qh_mma_kernel(const float* __restrict__ x,
                   const float* __restrict__ W1,
                   const float* __restrict__ b1,
                   const float* __restrict__ bn_g,
                   const float* __restrict__ bn_b,
                   const float* __restrict__ bn_m,
                   const float* __restrict__ bn_v,
                   const float* __restrict__ W2,
                   const float* __restrict__ b2,
                   const float* __restrict__ qw,
                   const float* __restrict__ W3,
                   const float* __restrict__ b3,
                   float* __restrict__ out)
{
    extern __shared__ char dsmem_raw[];
    const uint32_t tile_base = smem_u32(dsmem_raw);

    __shared__ float W2s[NQ * HDIM];
    __shared__ float scale_s[HDIM], shift_s[HDIM], b1s[HDIM];
    __shared__ float qtrig[NLAYERS * NQ * 4];
    __shared__ float W3s[NCLS * NQ], b3s[NCLS], b2s[NQ];

    const int tid = threadIdx.x;
    const int wid = tid >> 5;
    const int lane = tid & 31;
    const int rowBase = blockIdx.x * BM;

    // ---- constants ----
    if (tid < HDIM) {
        b1s[tid] = b1[tid];
        float sc = bn_g[tid] * rsqrtf(bn_v[tid] + 1e-5f);
        scale_s[tid] = sc;
        shift_s[tid] = bn_b[tid] - bn_m[tid] * sc;
    }
    for (int i = tid; i < NQ * HDIM; i += NTHREADS) W2s[i] = W2[i];
    if (tid < NLAYERS * NQ) {
        float a0 = qw[tid * 2 + 0] * 0.5f, a1 = qw[tid * 2 + 1] * 0.5f;
        qtrig[tid * 4 + 0] = cosf(a0); qtrig[tid * 4 + 1] = sinf(a0);
        qtrig[tid * 4 + 2] = cosf(a1); qtrig[tid * 4 + 3] = sinf(a1);
    }
    if (tid < NCLS * NQ) W3s[tid] = W3[tid];
    if (tid < NCLS)      b3s[tid] = b3[tid];
    if (tid < NQ)        b2s[tid] = b2[tid];

    // ---- warp tiling: 4(m) x 2(n); warp = 32x32 ----
    const int m0 = (wid & 3) * 32;
    const int n0 = (wid >> 2) * 32;

    // ldmatrix per-lane address components
    const int li = lane >> 3;      // 8-lane group 0..3
    const int lrow = lane & 7;
    // A: group i -> rows (i&1)*8, chunk-in-k16 = i>>1
    const int r0A = m0 + ((li & 1) << 3) + lrow;
    const uint32_t aLane = (uint32_t)(r0A * 64);
    const uint32_t xrA = (uint32_t)((r0A >> 1) & 3);
    const uint32_t ciA = (uint32_t)(li >> 1);
    // B: group i -> rows (i>>1)*8, chunk = i&1
    const int r0B = n0 + ((li >> 1) << 3) + lrow;
    const uint32_t bLane = (uint32_t)(r0B * 64);
    const uint32_t xrB = (uint32_t)((r0B >> 1) & 3);
    const uint32_t ciB = (uint32_t)(li & 1);

    // ---- loader mapping ----
    // x: 512 chunks/stage (128 rows x 4); thread owns chunks tid, tid+256
    const int xr1 = tid >> 2,        xc1 = tid & 3;
    const int xr2 = 64 + (tid >> 2), xc2 = tid & 3;
    const float* xp1 = x + (size_t)(rowBase + xr1) * KDIM + xc1 * 8;
    const float* xp2 = x + (size_t)(rowBase + xr2) * KDIM + xc2 * 8;
    const uint32_t xs1 = swz(xr1, xc1), xs2 = swz(xr2, xc2);
    // W1: 256 chunks/stage (64 rows x 4); thread owns chunk tid
    const int wr = tid >> 2, wc = tid & 3;
    const float* wp = W1 + (size_t)wr * KDIM + wc * 8;
    const uint32_t ws = swz(wr, wc);

    float4 xf1a, xf1b, xf2a, xf2b, wfa, wfb;

    // prologue: load + convert stage 0 into buffer 0
    xf1a = *(const float4*)(xp1);     xf1b = *(const float4*)(xp1 + 4);
    xf2a = *(const float4*)(xp2);     xf2b = *(const float4*)(xp2 + 4);
    wfa  = *(const float4*)(wp);      wfb  = *(const float4*)(wp + 4);
    cvt_store(tile_base + A_HI + xs1, tile_base + A_LO + xs1, xf1a, xf1b);
    cvt_store(tile_base + A_HI + xs2, tile_base + A_LO + xs2, xf2a, xf2b);
    cvt_store(tile_base + B_HI + ws,  tile_base + B_LO + ws,  wfa,  wfb);
    __syncthreads();

    float acc[2][4][4];
    #pragma unroll
    for (int mt = 0; mt < 2; ++mt)
        #pragma unroll
        for (int t = 0; t < 4; ++t)
            #pragma unroll
            for (int e = 0; e < 4; ++e) acc[mt][t][e] = 0.f;

    for (int s = 0; s < NSTAGES; ++s) {
        const uint32_t ab = tile_base + (uint32_t)((s & 1) * STAGE);

        // prefetch stage s+1
        if (s < NSTAGES - 1) {
            const int ko = (s + 1) * BKF;
            xf1a = *(const float4*)(xp1 + ko); xf1b = *(const float4*)(xp1 + ko + 4);
            xf2a = *(const float4*)(xp2 + ko); xf2b = *(const float4*)(xp2 + ko + 4);
            wfa  = *(const float4*)(wp + ko);  wfb  = *(const float4*)(wp + ko + 4);
        }

        // compute 2 k16 chunks of current buffer
        #pragma unroll
        for (int kt = 0; kt < 2; ++kt) {
            const uint32_t aoff = (uint32_t)((((2 * kt + ciA) ^ xrA)) << 4);
            const uint32_t boff = (uint32_t)((((2 * kt + ciB) ^ xrB)) << 4);
            uint32_t ahi[2][4], alo[2][4], bhi[2][4], blo[2][4];
            #pragma unroll
            for (int mt = 0; mt < 2; ++mt) {
                ldsm4(ahi[mt], ab + A_HI + aLane + mt * 1024 + aoff);
                ldsm4(alo[mt], ab + A_LO + aLane + mt * 1024 + aoff);
            }
            #pragma unroll
            for (int j = 0; j < 2; ++j) {
                ldsm4(bhi[j], ab + B_HI + bLane + j * 1024 + boff);
                ldsm4(blo[j], ab + B_LO + bLane + j * 1024 + boff);
            }
            #pragma unroll
            for (int mt = 0; mt < 2; ++mt)
                #pragma unroll
                for (int t = 0; t < 4; ++t) {
                    const uint32_t* bh = &bhi[t >> 1][(t & 1) * 2];
                    const uint32_t* bl = &blo[t >> 1][(t & 1) * 2];
                    mma_bf16(acc[mt][t], ahi[mt], bh);
                    mma_bf16(acc[mt][t], ahi[mt], bl);
                    mma_bf16(acc[mt][t], alo[mt], bh);
                }
        }

        // store stage s+1 into other buffer
        if (s < NSTAGES - 1) {
            const uint32_t nb = tile_base + (uint32_t)(((s + 1) & 1) * STAGE);
            cvt_store(nb + A_HI + xs1, nb + A_LO + xs1, xf1a, xf1b);
            cvt_store(nb + A_HI + xs2, nb + A_LO + xs2, xf2a, xf2b);
            cvt_store(nb + B_HI + ws,  nb + B_LO + ws,  wfa,  wfb);
        }
        __syncthreads();
    }

    // ---- epilogue part 1: bias+relu+bn -> Hs (overlays GEMM buffers) ----
    float* Hs = (float*)dsmem_raw;   // [128][65]
    {
        const int rr = lane >> 2;
        const int cc = (lane & 3) * 2;
        #pragma unroll
        for (int mt = 0; mt < 2; ++mt)
            #pragma unroll
            for (int t = 0; t < 4; ++t) {
                const int row = m0 + mt * 16 + rr;
                const int col = n0 + t * 8 + cc;
                float v0 = fmaxf(acc[mt][t][0] + b1s[col], 0.f)     * scale_s[col]     + shift_s[col];
                float v1 = fmaxf(acc[mt][t][1] + b1s[col + 1], 0.f) * scale_s[col + 1] + shift_s[col + 1];
                float v2 = fmaxf(acc[mt][t][2] + b1s[col], 0.f)     * scale_s[col]     + shift_s[col];
                float v3 = fmaxf(acc[mt][t][3] + b1s[col + 1], 0.f) * scale_s[col + 1] + shift_s[col + 1];
                Hs[row * 65 + col]           = v0;
                Hs[row * 65 + col + 1]       = v1;
                Hs[(row + 8) * 65 + col]     = v2;
                Hs[(row + 8) * 65 + col + 1] = v3;
            }
    }
    __syncthreads();

    // ---- epilogue part 2: quantum circuit, one thread per row ----
    if (tid < BM) {
        const float* hr = &Hs[tid * 65];

        float xqa[NQ] = {b2s[0], b2s[1], b2s[2], b2s[3]};
        #pragma unroll
        for (int h = 0; h < HDIM; ++h) {
            const float v = hr[h];
            #pragma unroll
            for (int q = 0; q < NQ; ++q)
                xqa[q] = fmaf(v, W2s[q * HDIM + h], xqa[q]);
        }

        float re[16], im[16];
        #pragma unroll
        for (int i = 0; i < 16; ++i) { re[i] = 0.f; im[i] = 0.f; }
        re[0] = 1.f;

        // encoder: angle = tanh(tanh(pre)) * pi, RY half-angle
        #pragma unroll
        for (int w = 0; w < NQ; ++w) {
            const float half_a = tanhf(tanhf(xqa[w])) * PI_HALF;
            const float c = cosf(half_a), s = sinf(half_a);
            const int st = 8 >> w;
            #pragma unroll
            for (int i = 0; i < 16; ++i) {
                if ((i & st) == 0) {
                    float r0 = re[i], i0 = im[i];
                    float r1 = re[i + st], i1 = im[i + st];
                    re[i]      = c * r0 - s * r1;
                    im[i]      = c * i0 - s * i1;
                    re[i + st] = s * r0 + c * r1;
                    im[i + st] = s * i0 + c * i1;
                }
            }
        }

        #pragma unroll
        for (int l = 0; l < NLAYERS; ++l) {
            #pragma unroll
            for (int w = 0; w < NQ; ++w) {
                const float cry = qtrig[(l * NQ + w) * 4 + 0];
                const float sry = qtrig[(l * NQ + w) * 4 + 1];
                const float crz = qtrig[(l * NQ + w) * 4 + 2];
                const float srz = qtrig[(l * NQ + w) * 4 + 3];
                const int st = 8 >> w;
                #pragma unroll
                for (int i = 0; i < 16; ++i) {
                    if ((i & st) == 0) {
                        float r0 = re[i], i0 = im[i];
                        float r1 = re[i + st], i1 = im[i + st];
                        float nr0 = cry * r0 - sry * r1;
                        float ni0 = cry * i0 - sry * i1;
                        float nr1 = sry * r0 + cry * r1;
                        float ni1 = sry * i0 + cry * i1;
                        re[i]      = nr0 * crz + ni0 * srz;
                        im[i]      = ni0 * crz - nr0 * srz;
                        re[i + st] = nr1 * crz - ni1 * srz;
                        im[i + st] = ni1 * crz + nr1 * srz;
                    }
                }
            }
            #pragma unroll
            for (int w = 0; w < NQ; ++w) {
                const int cs = 8 >> w;
                const int ts = 8 >> ((w + 1) & 3);
                #pragma unroll
                for (int i = 0; i < 16; ++i) {
                    if ((i & cs) != 0 && (i & ts) == 0) {
                        float tr = re[i]; re[i] = re[i + ts]; re[i + ts] = tr;
                        float ti = im[i]; im[i] = im[i + ts]; im[i + ts] = ti;
                    }
                }
            }
        }

        float z[NQ] = {0.f, 0.f, 0.f, 0.f};
        #pragma unroll
        for (int i = 0; i < 16; ++i) {
            const float p = re[i] * re[i] + im[i] * im[i];
            #pragma unroll
            for (int w = 0; w < NQ; ++w)
                z[w] += ((i >> (3 - w)) & 1) ? -p : p;
        }

        const int r = rowBase + tid;
        #pragma unroll
        for (int c = 0; c < NCLS; ++c) {
            float sv = b3s[c];
            #pragma unroll
            for (int q = 0; q < NQ; ++q) sv = fmaf(z[q], W3s[c * NQ + q], sv);
            out[r * NCLS + c] = sv;
        }
    }
}

extern "C" void kernel_launch(void* const* d_in, const int* in_sizes, int n_in,
                              void* d_out, int out_size)
{
    const float* x    = (const float*)d_in[0];
    const float* W1   = (const float*)d_in[1];
    const float* b1   = (const float*)d_in[2];
    const float* bn_g = (const float*)d_in[3];
    const float* bn_b = (const float*)d_in[4];
    const float* bn_m = (const float*)d_in[5];
    const float* bn_v = (const float*)d_in[6];
    const float* W2   = (const float*)d_in[7];
    const float* b2   = (const float*)d_in[8];
    const float* qw   = (const float*)d_in[9];
    const float* W3   = (const float*)d_in[10];
    const float* b3   = (const float*)d_in[11];
    float* out = (float*)d_out;

    // dynamic 48KB + ~2.4KB static shared exceeds the 48KB default cap:
    // opt in to a larger dynamic-smem limit (host-side attribute, not a
    // stream op — legal under graph capture, creates no graph nodes).
    cudaFuncSetAttribute(qh_mma_kernel,
                         cudaFuncAttributeMaxDynamicSharedMemorySize, DSMEM_BYTES);

    dim3 grid(BATCH / BM);
    dim3 block(NTHREADS);
    qh_mma_kernel<<<grid, block, DSMEM_BYTES>>>(x, W1, b1, bn_g, bn_b, bn_m, bn_v,
                                                W2, b2, qw, W3, b3, out);
}